// round 7
// baseline (speedup 1.0000x reference)
#include <cuda_runtime.h>
#include <cuda_bf16.h>
#include <math.h>

// Problem constants
#define BB   2
#define NN   2048
#define RRoi 128
#define CINv 256
#define NSv  16
#define C1v  128
#define RADv 0.3f
#define EPSv 1e-5f
#define FEATS_SZ (BB*C1v*NN)          // 524288
#define GRID_SZ  (BB*RRoi*125*C1v)    // 4096000

// ---------------- scratch ----------------
__device__ int   g_idx[BB*NN*NSv];
__device__ float g_Gt[BB*NN*256];        // [b][j][o]  (o contiguous)
__device__ float g_hmax[BB*256*NN];      // [b][o][n]
__device__ float g_h2[BB*C1v*NN];        // [b][o][n]
__device__ float g_h3[BB*C1v*NN];        // [b][o][n]
__device__ float g_featsT[BB*NN*C1v];    // [b][n][c]
__device__ float g_WxT[3*256];           // [k][o]
// packed bf16x2 weights, [o][c/2] layout (hi / lo split)
__device__ unsigned g_Wfh[256*128], g_Wfl[256*128];
__device__ unsigned g_W1h[128*128], g_W1l[128*128];
__device__ unsigned g_W2h[128*64],  g_W2l[128*64];
__device__ int   g_roilst[BB*RRoi*NN];
__device__ int   g_roicnt[BB*RRoi];
// stats: [0:256) sum1 [256:512) sq1 [512:640) sum2 [640:768) sq2 [768:896) sum3 [896:1024) sq3
__device__ float g_stats[1024];

// ---------------- helpers ----------------
__device__ __forceinline__ unsigned pack_split(float x0, float x1, unsigned& lo) {
    __nv_bfloat16 h0 = __float2bfloat16(x0);
    __nv_bfloat16 h1 = __float2bfloat16(x1);
    __nv_bfloat16 l0 = __float2bfloat16(x0 - __bfloat162float(h0));
    __nv_bfloat16 l1 = __float2bfloat16(x1 - __bfloat162float(h1));
    lo = ((unsigned)__bfloat16_as_ushort(l1) << 16) | (unsigned)__bfloat16_as_ushort(l0);
    return ((unsigned)__bfloat16_as_ushort(h1) << 16) | (unsigned)__bfloat16_as_ushort(h0);
}

__device__ __forceinline__ void mma16816(float* d, const unsigned* a, const unsigned* b) {
    asm volatile(
        "mma.sync.aligned.m16n8k16.row.col.f32.bf16.bf16.f32 "
        "{%0,%1,%2,%3}, {%4,%5,%6,%7}, {%8,%9}, {%0,%1,%2,%3};"
        : "+f"(d[0]), "+f"(d[1]), "+f"(d[2]), "+f"(d[3])
        : "r"(a[0]), "r"(a[1]), "r"(a[2]), "r"(a[3]), "r"(b[0]), "r"(b[1]));
}

// ---------------- fused front: weight split-convert + neighbor scan + roi classify ----------------
__global__ void k_front(const float* __restrict__ pts, const float* __restrict__ rois,
                        const float* __restrict__ Wm, const float* __restrict__ W1,
                        const float* __restrict__ W2) {
    __shared__ __align__(16) char sbuf[24576];
    int blk = blockIdx.x;
    if (blk < 227) {
        int id = blk * 256 + threadIdx.x;          // < 58112 exactly
        if (id < 32768) {                          // Wf pairs: [o][c2]
            int o = id >> 7, c2 = id & 127;
            unsigned lo;
            unsigned hi = pack_split(Wm[o * 259 + 3 + 2 * c2], Wm[o * 259 + 4 + 2 * c2], lo);
            g_Wfh[id] = hi; g_Wfl[id] = lo;
        } else if (id < 33536) {                   // WxT[k][o] fp32
            int t2 = id - 32768; int o = t2 & 255, k = t2 >> 8;
            g_WxT[t2] = Wm[o * 259 + k];
        } else if (id < 49920) {                   // W1 pairs
            int t2 = id - 33536; int o = t2 >> 7, c2 = t2 & 127;
            unsigned lo;
            unsigned hi = pack_split(W1[o * 256 + 2 * c2], W1[o * 256 + 2 * c2 + 1], lo);
            g_W1h[t2] = hi; g_W1l[t2] = lo;
        } else {                                   // W2 pairs
            int t2 = id - 49920; int o = t2 >> 6, c2 = t2 & 63;
            unsigned lo;
            unsigned hi = pack_split(W2[o * 128 + 2 * c2], W2[o * 128 + 2 * c2 + 1], lo);
            g_W2h[t2] = hi; g_W2l[t2] = lo;
        }
    } else if (blk < 739) {
        // ---- neighbor search: warp-per-point ballot scan ----
        int q = blk - 227;
        int b = q >> 8, chunk = q & 255;
        float* sx = (float*)sbuf;
        float* sy = sx + NN;
        float* sz = sx + 2 * NN;
        const float* P = pts + (size_t)b * NN * 3;
        for (int j = threadIdx.x; j < NN; j += 256) {
            sx[j] = P[j * 3 + 0]; sy[j] = P[j * 3 + 1]; sz[j] = P[j * 3 + 2];
        }
        __syncthreads();
        int warp = threadIdx.x >> 5, lane = threadIdx.x & 31;
        int i = chunk * 8 + warp;
        float xi = sx[i], yi = sy[i], zi = sz[i];
        int base = (b * NN + i) * NSv;
        const float r2 = RADv * RADv;
        int cnt = 0, f0 = -1;
        for (int j0 = 0; j0 < NN; j0 += 32) {
            int j = j0 + lane;
            float dx = sx[j] - xi, dy = sy[j] - yi, dz = sz[j] - zi;
            bool qq = (dx * dx + dy * dy + dz * dz) < r2;
            unsigned m = __ballot_sync(0xffffffffu, qq);
            if (m) {
                if (f0 < 0) f0 = j0 + __ffs(m) - 1;
                int pos = cnt + __popc(m & ((1u << lane) - 1u));
                if (qq && pos < NSv) g_idx[base + pos] = j;
                cnt += __popc(m);
                if (cnt >= NSv) break;
            }
        }
        if (cnt < NSv) {
            for (int s = cnt + lane; s < NSv; s += 32) g_idx[base + s] = f0;
        }
    } else {
        // ---- roi point-in-box classify ----
        int br = blk - 739;
        int b = br >> 7;
        int* cnt = (int*)sbuf;
        if (threadIdx.x == 0) *cnt = 0;
        __syncthreads();
        const float* qr = rois + (size_t)br * 7;
        float cx = qr[0], cy = qr[1], cz = qr[2];
        float hx = qr[3] * 0.5f, hy = qr[4] * 0.5f, hz = qr[5] * 0.5f;
        float co = cosf(qr[6]), si = sinf(qr[6]);
        const float* P = pts + (size_t)b * NN * 3;
        int* lst = g_roilst + (size_t)br * NN;
        for (int n = threadIdx.x; n < NN; n += 256) {
            float rx = P[n * 3 + 0] - cx;
            float ry = P[n * 3 + 1] - cy;
            float rz = P[n * 3 + 2] - cz;
            float lx = rx * co + ry * si;
            float ly = -rx * si + ry * co;
            float lz = rz;
            if (fabsf(lx) < hx && fabsf(ly) < hy && fabsf(lz) < hz) {
                int v0 = (int)fminf(fmaxf(floorf((lx + hx) / (2.f * hx) * 5.f), 0.f), 4.f);
                int v1 = (int)fminf(fmaxf(floorf((ly + hy) / (2.f * hy) * 5.f), 0.f), 4.f);
                int v2 = (int)fminf(fmaxf(floorf((lz + hz) / (2.f * hz) * 5.f), 0.f), 4.f);
                int vox = (v0 * 5 + v1) * 5 + v2;
                int pos = atomicAdd(cnt, 1);
                lst[pos] = (vox << 12) | n;
            }
        }
        __syncthreads();
        if (threadIdx.x == 0) g_roicnt[br] = *cnt;
    }
}

// ---------------- GEMM G (tensor core): Gt[b][n][o] = sum_c Wf[o][c] * feat[b][c][n]
// block 32o x 64n, 128 thr (4 warps over n), K=256. grid = 32n x 8o x 2b = 512.
__global__ void k_gemmG(const float* __restrict__ feat) {
    __shared__ unsigned s_wh[32][9], s_wl[32][9];
    __shared__ unsigned s_ah[64][9], s_al[64][9];
    __shared__ float s_outT[64][36];
    int b = blockIdx.z;
    int n0 = blockIdx.x * 64, o0 = blockIdx.y * 32;
    int tid = threadIdx.x;
    int lane = tid & 31, warp = tid >> 5;
    int g = lane >> 2, t = lane & 3;
    int wn0 = warp * 16;
    int wo = tid >> 3, wc = tid & 7;
    int ac = tid >> 3, an = (tid & 7) * 8;
    float d[2][2][4] = {};
    const float* Asrc = feat + (size_t)(b * CINv) * NN;
    for (int ks = 0; ks < 16; ks++) {
        int k0 = ks * 16;
        s_wh[wo][wc]      = g_Wfh[(o0 + wo) * 128 + k0 / 2 + wc];
        s_wl[wo][wc]      = g_Wfl[(o0 + wo) * 128 + k0 / 2 + wc];
        s_wh[wo + 16][wc] = g_Wfh[(o0 + wo + 16) * 128 + k0 / 2 + wc];
        s_wl[wo + 16][wc] = g_Wfl[(o0 + wo + 16) * 128 + k0 / 2 + wc];
        {
            const float* ar = Asrc + (size_t)(k0 + ac) * NN + n0 + an;
            float4 v0 = *(const float4*)ar;
            float4 v1 = *(const float4*)(ar + 4);
            float vals[8] = {v0.x, v0.y, v0.z, v0.w, v1.x, v1.y, v1.z, v1.w};
            __nv_bfloat16* ah = (__nv_bfloat16*)s_ah;
            __nv_bfloat16* al = (__nv_bfloat16*)s_al;
            #pragma unroll
            for (int q = 0; q < 8; q++) {
                float x = vals[q];
                __nv_bfloat16 h = __float2bfloat16(x);
                ah[(an + q) * 18 + ac] = h;
                al[(an + q) * 18 + ac] = __float2bfloat16(x - __bfloat162float(h));
            }
        }
        __syncthreads();
        unsigned wh[2][4], wl[2][4], bh[2][2], bl[2][2];
        #pragma unroll
        for (int j = 0; j < 2; j++) {
            int r0 = j * 16 + g;
            wh[j][0] = s_wh[r0][t]; wh[j][1] = s_wh[r0 + 8][t];
            wh[j][2] = s_wh[r0][t + 4]; wh[j][3] = s_wh[r0 + 8][t + 4];
            wl[j][0] = s_wl[r0][t]; wl[j][1] = s_wl[r0 + 8][t];
            wl[j][2] = s_wl[r0][t + 4]; wl[j][3] = s_wl[r0 + 8][t + 4];
        }
        #pragma unroll
        for (int i = 0; i < 2; i++) {
            int n = wn0 + i * 8 + g;
            bh[i][0] = s_ah[n][t]; bh[i][1] = s_ah[n][t + 4];
            bl[i][0] = s_al[n][t]; bl[i][1] = s_al[n][t + 4];
        }
        #pragma unroll
        for (int j = 0; j < 2; j++)
            #pragma unroll
            for (int i = 0; i < 2; i++) {
                mma16816(d[j][i], wh[j], bh[i]);
                mma16816(d[j][i], wh[j], bl[i]);
                mma16816(d[j][i], wl[j], bh[i]);
            }
        __syncthreads();
    }
    #pragma unroll
    for (int j = 0; j < 2; j++)
        #pragma unroll
        for (int i = 0; i < 2; i++) {
            int nc = wn0 + i * 8 + 2 * t;
            s_outT[nc][j * 16 + g] = d[j][i][0];
            s_outT[nc + 1][j * 16 + g] = d[j][i][1];
            s_outT[nc][j * 16 + g + 8] = d[j][i][2];
            s_outT[nc + 1][j * 16 + g + 8] = d[j][i][3];
        }
    __syncthreads();
    {
        int n_l = tid >> 1, q = tid & 1;
        float* orow = &g_Gt[(size_t)(b * NN + n0 + n_l) * 256 + o0 + q * 16];
        #pragma unroll
        for (int f = 0; f < 4; f++)
            *(float4*)&orow[f * 4] = *(float4*)&s_outT[n_l][q * 16 + f * 4];
    }
}

// ---------------- gather + xyz MLP + max over samples + BN1 stats (float4 gather) ----------------
#define PPB 8
__global__ void k_gathermax(const float* __restrict__ pts) {
    __shared__ int   sj[PPB * NSv];
    __shared__ float srx[PPB * NSv], sry[PPB * NSv], srz[PPB * NSv];
    __shared__ float stile[256 * (PPB + 1)];
    __shared__ float ssum[4][256], ssq[4][256];
    int b = blockIdx.y;
    int n0 = blockIdx.x * PPB;
    int tid = threadIdx.x;
    if (tid < PPB * NSv) {
        int p = tid >> 4, s = tid & 15;
        int n = n0 + p;
        int j = g_idx[(b * NN + n) * NSv + s];
        sj[tid] = j;
        const float* P = pts + (size_t)b * NN * 3;
        srx[tid] = (P[j * 3 + 0] - P[n * 3 + 0]) / RADv;
        sry[tid] = (P[j * 3 + 1] - P[n * 3 + 1]) / RADv;
        srz[tid] = (P[j * 3 + 2] - P[n * 3 + 2]) / RADv;
    }
    __syncthreads();
    int co = tid & 63;
    int pg = tid >> 6;
    float4 w0 = *(const float4*)&g_WxT[co * 4];
    float4 w1 = *(const float4*)&g_WxT[256 + co * 4];
    float4 w2 = *(const float4*)&g_WxT[512 + co * 4];
    float4 ls = make_float4(0.f, 0.f, 0.f, 0.f);
    float4 lq = make_float4(0.f, 0.f, 0.f, 0.f);
    const float* Gb = g_Gt + (size_t)b * NN * 256;
    #pragma unroll
    for (int pp = 0; pp < 2; pp++) {
        int p = pg * 2 + pp;
        float4 m = make_float4(-3.4e38f, -3.4e38f, -3.4e38f, -3.4e38f);
        #pragma unroll
        for (int s = 0; s < NSv; s++) {
            int e = p * NSv + s;
            int j = sj[e];
            float rx = srx[e], ry = sry[e], rz = srz[e];
            float4 gv = *(const float4*)&Gb[(size_t)j * 256 + co * 4];
            float4 v;
            v.x = gv.x + w0.x * rx + w1.x * ry + w2.x * rz;
            v.y = gv.y + w0.y * rx + w1.y * ry + w2.y * rz;
            v.z = gv.z + w0.z * rx + w1.z * ry + w2.z * rz;
            v.w = gv.w + w0.w * rx + w1.w * ry + w2.w * rz;
            m.x = fmaxf(m.x, v.x); m.y = fmaxf(m.y, v.y);
            m.z = fmaxf(m.z, v.z); m.w = fmaxf(m.w, v.w);
            ls.x += v.x; ls.y += v.y; ls.z += v.z; ls.w += v.w;
            lq.x += v.x * v.x; lq.y += v.y * v.y; lq.z += v.z * v.z; lq.w += v.w * v.w;
        }
        stile[(co * 4 + 0) * (PPB + 1) + p] = m.x;
        stile[(co * 4 + 1) * (PPB + 1) + p] = m.y;
        stile[(co * 4 + 2) * (PPB + 1) + p] = m.z;
        stile[(co * 4 + 3) * (PPB + 1) + p] = m.w;
    }
    ssum[pg][co * 4 + 0] = ls.x; ssum[pg][co * 4 + 1] = ls.y;
    ssum[pg][co * 4 + 2] = ls.z; ssum[pg][co * 4 + 3] = ls.w;
    ssq[pg][co * 4 + 0] = lq.x; ssq[pg][co * 4 + 1] = lq.y;
    ssq[pg][co * 4 + 2] = lq.z; ssq[pg][co * 4 + 3] = lq.w;
    __syncthreads();
    #pragma unroll
    for (int r = 0; r < 256; r += 32) {
        int row = r + (tid >> 3);
        int col = tid & 7;
        g_hmax[(size_t)(b * 256 + row) * NN + n0 + col] = stile[row * (PPB + 1) + col];
    }
    float ts = ssum[0][tid] + ssum[1][tid] + ssum[2][tid] + ssum[3][tid];
    float tq = ssq[0][tid] + ssq[1][tid] + ssq[2][tid] + ssq[3][tid];
    atomicAdd(&g_stats[tid], ts);
    atomicAdd(&g_stats[256 + tid], tq);
}

// ---------------- GEMM1 (tensor core): h2 = b1 + W1 @ relu(bn1(hmax)), fused BN2 stats
// block 32o x 64n, 128 thr, K=256. grid = 32 x 4 x 2 = 256.
__global__ void k_gemm1(const float* __restrict__ gm, const float* __restrict__ btm,
                        const float* __restrict__ b1) {
    __shared__ unsigned s_wh[32][9], s_wl[32][9];
    __shared__ unsigned s_ah[64][9], s_al[64][9];
    __shared__ float s_out[32][68];
    __shared__ float ssc[256], ssh[256];
    int b = blockIdx.z;
    int n0 = blockIdx.x * 64, o0 = blockIdx.y * 32;
    int tid = threadIdx.x;
    #pragma unroll
    for (int q = 0; q < 2; q++) {
        int c = tid + q * 128;
        float m = g_stats[c] * (1.f / 65536.f);
        float v = g_stats[256 + c] * (1.f / 65536.f) - m * m;
        float sc = gm[c] * rsqrtf(v + EPSv);
        ssc[c] = sc; ssh[c] = btm[c] - m * sc;
    }
    __syncthreads();
    int lane = tid & 31, warp = tid >> 5;
    int g = lane >> 2, t = lane & 3;
    int wn0 = warp * 16;
    int wo = tid >> 3, wc = tid & 7;
    int ac = tid >> 3, an = (tid & 7) * 8;
    float d[2][2][4] = {};
    const float* Asrc = g_hmax + (size_t)(b * 256) * NN;
    for (int ks = 0; ks < 16; ks++) {
        int k0 = ks * 16;
        s_wh[wo][wc]      = g_W1h[(o0 + wo) * 128 + k0 / 2 + wc];
        s_wl[wo][wc]      = g_W1l[(o0 + wo) * 128 + k0 / 2 + wc];
        s_wh[wo + 16][wc] = g_W1h[(o0 + wo + 16) * 128 + k0 / 2 + wc];
        s_wl[wo + 16][wc] = g_W1l[(o0 + wo + 16) * 128 + k0 / 2 + wc];
        {
            float sc = ssc[k0 + ac], sh = ssh[k0 + ac];
            const float* ar = Asrc + (size_t)(k0 + ac) * NN + n0 + an;
            float4 v0 = *(const float4*)ar;
            float4 v1 = *(const float4*)(ar + 4);
            float vals[8] = {v0.x, v0.y, v0.z, v0.w, v1.x, v1.y, v1.z, v1.w};
            __nv_bfloat16* ah = (__nv_bfloat16*)s_ah;
            __nv_bfloat16* al = (__nv_bfloat16*)s_al;
            #pragma unroll
            for (int q = 0; q < 8; q++) {
                float x = fmaxf(vals[q] * sc + sh, 0.f);
                __nv_bfloat16 h = __float2bfloat16(x);
                ah[(an + q) * 18 + ac] = h;
                al[(an + q) * 18 + ac] = __float2bfloat16(x - __bfloat162float(h));
            }
        }
        __syncthreads();
        unsigned wh[2][4], wl[2][4], bh[2][2], bl[2][2];
        #pragma unroll
        for (int j = 0; j < 2; j++) {
            int r0 = j * 16 + g;
            wh[j][0] = s_wh[r0][t]; wh[j][1] = s_wh[r0 + 8][t];
            wh[j][2] = s_wh[r0][t + 4]; wh[j][3] = s_wh[r0 + 8][t + 4];
            wl[j][0] = s_wl[r0][t]; wl[j][1] = s_wl[r0 + 8][t];
            wl[j][2] = s_wl[r0][t + 4]; wl[j][3] = s_wl[r0 + 8][t + 4];
        }
        #pragma unroll
        for (int i = 0; i < 2; i++) {
            int n = wn0 + i * 8 + g;
            bh[i][0] = s_ah[n][t]; bh[i][1] = s_ah[n][t + 4];
            bl[i][0] = s_al[n][t]; bl[i][1] = s_al[n][t + 4];
        }
        #pragma unroll
        for (int j = 0; j < 2; j++)
            #pragma unroll
            for (int i = 0; i < 2; i++) {
                mma16816(d[j][i], wh[j], bh[i]);
                mma16816(d[j][i], wh[j], bl[i]);
                mma16816(d[j][i], wl[j], bh[i]);
            }
        __syncthreads();
    }
    #pragma unroll
    for (int j = 0; j < 2; j++)
        #pragma unroll
        for (int i = 0; i < 2; i++) {
            *(float2*)&s_out[j * 16 + g][wn0 + i * 8 + 2 * t] = make_float2(d[j][i][0], d[j][i][1]);
            *(float2*)&s_out[j * 16 + g + 8][wn0 + i * 8 + 2 * t] = make_float2(d[j][i][2], d[j][i][3]);
        }
    __syncthreads();
    {
        int o_l = tid >> 2, q = tid & 3;
        int o = o0 + o_l;
        float bias = b1[o];
        float s = 0.f, sq = 0.f;
        float* orow = &g_h2[(size_t)(b * C1v + o) * NN + n0 + q * 16];
        #pragma unroll
        for (int f = 0; f < 4; f++) {
            float4 v = *(float4*)&s_out[o_l][q * 16 + f * 4];
            v.x += bias; v.y += bias; v.z += bias; v.w += bias;
            s += v.x + v.y + v.z + v.w;
            sq += v.x * v.x + v.y * v.y + v.z * v.z + v.w * v.w;
            *(float4*)&orow[f * 4] = v;
        }
        s += __shfl_down_sync(0xffffffffu, s, 2, 4);
        s += __shfl_down_sync(0xffffffffu, s, 1, 4);
        sq += __shfl_down_sync(0xffffffffu, sq, 2, 4);
        sq += __shfl_down_sync(0xffffffffu, sq, 1, 4);
        if (q == 0) { atomicAdd(&g_stats[512 + o], s); atomicAdd(&g_stats[640 + o], sq); }
    }
}

// ---------------- GEMM2 (tensor core): h3 = b2 + W2 @ relu(bn2(h2)), fused BN3 stats
// block 32o x 64n, 128 thr, K=128. grid = 32 x 4 x 2 = 256.
__global__ void k_gemm2(const float* __restrict__ g1, const float* __restrict__ bt1,
                        const float* __restrict__ b2) {
    __shared__ unsigned s_wh[32][9], s_wl[32][9];
    __shared__ unsigned s_ah[64][9], s_al[64][9];
    __shared__ float s_out[32][68];
    __shared__ float ssc[128], ssh[128];
    int b = blockIdx.z;
    int n0 = blockIdx.x * 64, o0 = blockIdx.y * 32;
    int tid = threadIdx.x;
    {
        float m = g_stats[512 + tid] * (1.f / 4096.f);
        float v = g_stats[640 + tid] * (1.f / 4096.f) - m * m;
        float sc = g1[tid] * rsqrtf(v + EPSv);
        ssc[tid] = sc; ssh[tid] = bt1[tid] - m * sc;
    }
    __syncthreads();
    int lane = tid & 31, warp = tid >> 5;
    int g = lane >> 2, t = lane & 3;
    int wn0 = warp * 16;
    int wo = tid >> 3, wc = tid & 7;
    int ac = tid >> 3, an = (tid & 7) * 8;
    float d[2][2][4] = {};
    const float* Asrc = g_h2 + (size_t)(b * C1v) * NN;
    for (int ks = 0; ks < 8; ks++) {
        int k0 = ks * 16;
        s_wh[wo][wc]      = g_W2h[(o0 + wo) * 64 + k0 / 2 + wc];
        s_wl[wo][wc]      = g_W2l[(o0 + wo) * 64 + k0 / 2 + wc];
        s_wh[wo + 16][wc] = g_W2h[(o0 + wo + 16) * 64 + k0 / 2 + wc];
        s_wl[wo + 16][wc] = g_W2l[(o0 + wo + 16) * 64 + k0 / 2 + wc];
        {
            float sc = ssc[k0 + ac], sh = ssh[k0 + ac];
            const float* ar = Asrc + (size_t)(k0 + ac) * NN + n0 + an;
            float4 v0 = *(const float4*)ar;
            float4 v1 = *(const float4*)(ar + 4);
            float vals[8] = {v0.x, v0.y, v0.z, v0.w, v1.x, v1.y, v1.z, v1.w};
            __nv_bfloat16* ah = (__nv_bfloat16*)s_ah;
            __nv_bfloat16* al = (__nv_bfloat16*)s_al;
            #pragma unroll
            for (int q = 0; q < 8; q++) {
                float x = fmaxf(vals[q] * sc + sh, 0.f);
                __nv_bfloat16 h = __float2bfloat16(x);
                ah[(an + q) * 18 + ac] = h;
                al[(an + q) * 18 + ac] = __float2bfloat16(x - __bfloat162float(h));
            }
        }
        __syncthreads();
        unsigned wh[2][4], wl[2][4], bh[2][2], bl[2][2];
        #pragma unroll
        for (int j = 0; j < 2; j++) {
            int r0 = j * 16 + g;
            wh[j][0] = s_wh[r0][t]; wh[j][1] = s_wh[r0 + 8][t];
            wh[j][2] = s_wh[r0][t + 4]; wh[j][3] = s_wh[r0 + 8][t + 4];
            wl[j][0] = s_wl[r0][t]; wl[j][1] = s_wl[r0 + 8][t];
            wl[j][2] = s_wl[r0][t + 4]; wl[j][3] = s_wl[r0 + 8][t + 4];
        }
        #pragma unroll
        for (int i = 0; i < 2; i++) {
            int n = wn0 + i * 8 + g;
            bh[i][0] = s_ah[n][t]; bh[i][1] = s_ah[n][t + 4];
            bl[i][0] = s_al[n][t]; bl[i][1] = s_al[n][t + 4];
        }
        #pragma unroll
        for (int j = 0; j < 2; j++)
            #pragma unroll
            for (int i = 0; i < 2; i++) {
                mma16816(d[j][i], wh[j], bh[i]);
                mma16816(d[j][i], wh[j], bl[i]);
                mma16816(d[j][i], wl[j], bh[i]);
            }
        __syncthreads();
    }
    #pragma unroll
    for (int j = 0; j < 2; j++)
        #pragma unroll
        for (int i = 0; i < 2; i++) {
            *(float2*)&s_out[j * 16 + g][wn0 + i * 8 + 2 * t] = make_float2(d[j][i][0], d[j][i][1]);
            *(float2*)&s_out[j * 16 + g + 8][wn0 + i * 8 + 2 * t] = make_float2(d[j][i][2], d[j][i][3]);
        }
    __syncthreads();
    {
        int o_l = tid >> 2, q = tid & 3;
        int o = o0 + o_l;
        float bias = b2[o];
        float s = 0.f, sq = 0.f;
        float* orow = &g_h3[(size_t)(b * C1v + o) * NN + n0 + q * 16];
        #pragma unroll
        for (int f = 0; f < 4; f++) {
            float4 v = *(float4*)&s_out[o_l][q * 16 + f * 4];
            v.x += bias; v.y += bias; v.z += bias; v.w += bias;
            s += v.x + v.y + v.z + v.w;
            sq += v.x * v.x + v.y * v.y + v.z * v.z + v.w * v.w;
            *(float4*)&orow[f * 4] = v;
        }
        s += __shfl_down_sync(0xffffffffu, s, 2, 4);
        s += __shfl_down_sync(0xffffffffu, s, 1, 4);
        sq += __shfl_down_sync(0xffffffffu, sq, 2, 4);
        sq += __shfl_down_sync(0xffffffffu, sq, 1, 4);
        if (q == 0) { atomicAdd(&g_stats[768 + o], s); atomicAdd(&g_stats[896 + o], sq); }
    }
}

// ---------------- final feats: BN3+ReLU, tiled transpose (both writes coalesced) ----------------
__global__ void k_feats(const float* __restrict__ g2, const float* __restrict__ bt2,
                        float* __restrict__ out) {
    __shared__ float t[32][33];
    __shared__ float ssc[32], ssh[32];
    int b = blockIdx.z;
    int n0 = blockIdx.x * 32, o0 = blockIdx.y * 32;
    int tid = threadIdx.x;
    int tx = tid & 31, ty = tid >> 5;          // 32x8
    if (tid < 32) {
        int o = o0 + tid;
        float m = g_stats[768 + o] * (1.f / 4096.f);
        float v = g_stats[896 + o] * (1.f / 4096.f) - m * m;
        float sc = g2[o] * rsqrtf(v + EPSv);
        ssc[tid] = sc; ssh[tid] = bt2[o] - m * sc;
    }
    __syncthreads();
    #pragma unroll
    for (int r = 0; r < 4; r++) {
        int oo = ty + r * 8;
        int o = o0 + oo;
        size_t e = (size_t)(b * C1v + o) * NN + n0 + tx;
        float f = fmaxf(g_h3[e] * ssc[oo] + ssh[oo], 0.f);
        out[e] = f;
        t[oo][tx] = f;
    }
    __syncthreads();
    #pragma unroll
    for (int r = 0; r < 4; r++) {
        int nn = ty + r * 8;
        g_featsT[(size_t)(b * NN + n0 + nn) * C1v + o0 + tx] = t[tx][nn];
    }
}

// ---------------- RoI voxel max-pool: smem grid, parallel over points via smem atomicMax ----------------
__global__ void k_roipool(float* __restrict__ out) {
    extern __shared__ float sg[];            // 125*128 floats
    int br = blockIdx.x;
    int b = br >> 7;
    int t = threadIdx.x;                     // 512
    for (int i = t; i < 125 * C1v / 4; i += 512)
        ((float4*)sg)[i] = make_float4(0.f, 0.f, 0.f, 0.f);
    __syncthreads();
    const float* F = g_featsT + (size_t)b * NN * C1v;
    const int* lst = g_roilst + (size_t)br * NN;
    int m = g_roicnt[br];
    int ch = t & 127;
    int slot = t >> 7;                       // 0..3
    for (int e = slot; e < m; e += 4) {
        int pk = lst[e];
        int n = pk & 4095;
        int vox = pk >> 12;
        float val = F[(size_t)n * C1v + ch];
        atomicMax((int*)&sg[vox * C1v + ch], __float_as_int(val));
    }
    __syncthreads();
    float4* og = (float4*)(out + FEATS_SZ + (size_t)br * 125 * C1v);
    for (int i = t; i < 125 * C1v / 4; i += 512) og[i] = ((float4*)sg)[i];
}

// ---------------- launch ----------------
extern "C" void kernel_launch(void* const* d_in, const int* in_sizes, int n_in,
                              void* d_out, int out_size) {
    const float* pts    = (const float*)d_in[0];
    const float* feat   = (const float*)d_in[1];
    const float* rois   = (const float*)d_in[2];
    const float* W_mlp  = (const float*)d_in[3];
    const float* g_mlp  = (const float*)d_in[4];
    const float* btm    = (const float*)d_in[5];
    const float* W1     = (const float*)d_in[6];
    const float* b1     = (const float*)d_in[7];
    const float* g1     = (const float*)d_in[8];
    const float* bt1    = (const float*)d_in[9];
    const float* W2     = (const float*)d_in[10];
    const float* b2     = (const float*)d_in[11];
    const float* g2     = (const float*)d_in[12];
    const float* bt2    = (const float*)d_in[13];
    float* out = (float*)d_out;

    cudaFuncSetAttribute(k_roipool, cudaFuncAttributeMaxDynamicSharedMemorySize,
                         125 * C1v * sizeof(float));

    void* statsPtr = nullptr;
    cudaGetSymbolAddress(&statsPtr, g_stats);
    cudaMemsetAsync(statsPtr, 0, 1024 * sizeof(float), 0);

    k_front<<<995, 256>>>(pts, rois, W_mlp, W1, W2);
    k_gemmG<<<dim3(NN / 64, 256 / 32, BB), 128>>>(feat);
    k_gathermax<<<dim3(NN / PPB, BB), 256>>>(pts);
    k_gemm1<<<dim3(NN / 64, C1v / 32, BB), 128>>>(g_mlp, btm, b1);
    k_gemm2<<<dim3(NN / 64, C1v / 32, BB), 128>>>(g1, bt1, b2);
    k_feats<<<dim3(NN / 32, C1v / 32, BB), 256>>>(g2, bt2, out);
    k_roipool<<<BB * RRoi, 512, 125 * C1v * sizeof(float)>>>(out);
}

// round 9
// speedup vs baseline: 1.0561x; 1.0561x over previous
#include <cuda_runtime.h>
#include <cuda_bf16.h>
#include <math.h>

// Problem constants
#define BB   2
#define NN   2048
#define RRoi 128
#define CINv 256
#define NSv  16
#define C1v  128
#define RADv 0.3f
#define EPSv 1e-5f
#define FEATS_SZ (BB*C1v*NN)          // 524288
#define GRID_SZ  (BB*RRoi*125*C1v)    // 4096000

// ---------------- scratch ----------------
__device__ int   g_idx[BB*NN*NSv];
__device__ float g_Gt[BB*NN*256];        // [b][n][o]  (o contiguous)
__device__ float g_hmax[BB*NN*256];      // [b][n][c]  (c contiguous)
__device__ float g_h2[BB*NN*C1v];        // [b][n][o]
__device__ float g_h3[BB*NN*C1v];        // [b][n][o]
__device__ float g_featsT[BB*NN*C1v];    // [b][n][c]
__device__ float g_WxT[3*256];           // [k][o]
// packed bf16x2, hi/lo split. weights [o][k/2]; activations [b][n][k/2]
__device__ unsigned g_Wfh[256*128], g_Wfl[256*128];
__device__ unsigned g_W1h[128*128], g_W1l[128*128];
__device__ unsigned g_W2h[128*64],  g_W2l[128*64];
__device__ unsigned g_Fh[BB*NN*128],  g_Fl[BB*NN*128];   // split features
__device__ unsigned g_A1h[BB*NN*128], g_A1l[BB*NN*128];  // split relu(bn1(hmax))
__device__ unsigned g_A2h[BB*NN*64],  g_A2l[BB*NN*64];   // split relu(bn2(h2))
__device__ int   g_roilst[BB*RRoi*NN];
__device__ int   g_roicnt[BB*RRoi];
// stats: [0:256) sum1 [256:512) sq1 [512:640) sum2 [640:768) sq2 [768:896) sum3 [896:1024) sq3
__device__ float g_stats[1024];

// ---------------- helpers ----------------
__device__ __forceinline__ unsigned pack_split(float x0, float x1, unsigned& lo) {
    __nv_bfloat16 h0 = __float2bfloat16(x0);
    __nv_bfloat16 h1 = __float2bfloat16(x1);
    __nv_bfloat16 l0 = __float2bfloat16(x0 - __bfloat162float(h0));
    __nv_bfloat16 l1 = __float2bfloat16(x1 - __bfloat162float(h1));
    lo = ((unsigned)__bfloat16_as_ushort(l1) << 16) | (unsigned)__bfloat16_as_ushort(l0);
    return ((unsigned)__bfloat16_as_ushort(h1) << 16) | (unsigned)__bfloat16_as_ushort(h0);
}

__device__ __forceinline__ void mma16816(float* d, const unsigned* a, const unsigned* b) {
    asm volatile(
        "mma.sync.aligned.m16n8k16.row.col.f32.bf16.bf16.f32 "
        "{%0,%1,%2,%3}, {%4,%5,%6,%7}, {%8,%9}, {%0,%1,%2,%3};"
        : "+f"(d[0]), "+f"(d[1]), "+f"(d[2]), "+f"(d[3])
        : "r"(a[0]), "r"(a[1]), "r"(a[2]), "r"(a[3]), "r"(b[0]), "r"(b[1]));
}

struct SmemGemm {
    unsigned wh[2][32][12], wl[2][32][12];
    unsigned ah[2][64][12], al[2][64][12];
    float outT[64][36];
};

// pure-MMA mainloop: 32o x 64n tile, 128 threads, pre-split operands in global.
// d is a flat [4][4] accumulator array: d[j*2+i] = (o-half j, n-half i).
template<int KSTEPS>
__device__ __forceinline__ void gemm_mainloop(
    SmemGemm& s,
    const unsigned* __restrict__ Wh, const unsigned* __restrict__ Wl,
    const unsigned* __restrict__ Ah, const unsigned* __restrict__ Al,
    int o0, size_t nbase, float (*d)[4], int tid)
{
    const int kw2 = KSTEPS * 8;
    int lane = tid & 31, warp = tid >> 5;
    int g = lane >> 2, t = lane & 3;
    int wn0 = warp * 16;
    int srw = tid >> 1;            // 0..63 (weights use tid<64 -> 0..31)
    int sq = (tid & 1) * 4;
    // prologue: fill buf 0
    if (tid < 64) {
        *(uint4*)&s.wh[0][srw][sq] = *(const uint4*)&Wh[(size_t)(o0 + srw) * kw2 + sq];
        *(uint4*)&s.wl[0][srw][sq] = *(const uint4*)&Wl[(size_t)(o0 + srw) * kw2 + sq];
    }
    *(uint4*)&s.ah[0][srw][sq] = *(const uint4*)&Ah[(nbase + srw) * kw2 + sq];
    *(uint4*)&s.al[0][srw][sq] = *(const uint4*)&Al[(nbase + srw) * kw2 + sq];
    __syncthreads();
    int buf = 0;
    #pragma unroll
    for (int ks = 0; ks < KSTEPS; ks++) {
        uint4 nwh, nwl, nah, nal;
        if (ks + 1 < KSTEPS) {
            int kw = (ks + 1) * 8 + sq;
            if (tid < 64) {
                nwh = *(const uint4*)&Wh[(size_t)(o0 + srw) * kw2 + kw];
                nwl = *(const uint4*)&Wl[(size_t)(o0 + srw) * kw2 + kw];
            }
            nah = *(const uint4*)&Ah[(nbase + srw) * kw2 + kw];
            nal = *(const uint4*)&Al[(nbase + srw) * kw2 + kw];
        }
        unsigned whf[2][4], wlf[2][4], bhf[2][2], blf[2][2];
        #pragma unroll
        for (int j = 0; j < 2; j++) {
            int r0 = j * 16 + g;
            whf[j][0] = s.wh[buf][r0][t];     whf[j][1] = s.wh[buf][r0 + 8][t];
            whf[j][2] = s.wh[buf][r0][t + 4]; whf[j][3] = s.wh[buf][r0 + 8][t + 4];
            wlf[j][0] = s.wl[buf][r0][t];     wlf[j][1] = s.wl[buf][r0 + 8][t];
            wlf[j][2] = s.wl[buf][r0][t + 4]; wlf[j][3] = s.wl[buf][r0 + 8][t + 4];
        }
        #pragma unroll
        for (int i = 0; i < 2; i++) {
            int n = wn0 + i * 8 + g;
            bhf[i][0] = s.ah[buf][n][t]; bhf[i][1] = s.ah[buf][n][t + 4];
            blf[i][0] = s.al[buf][n][t]; blf[i][1] = s.al[buf][n][t + 4];
        }
        #pragma unroll
        for (int j = 0; j < 2; j++)
            #pragma unroll
            for (int i = 0; i < 2; i++) {
                mma16816(d[j * 2 + i], whf[j], bhf[i]);
                mma16816(d[j * 2 + i], whf[j], blf[i]);
                mma16816(d[j * 2 + i], wlf[j], bhf[i]);
            }
        if (ks + 1 < KSTEPS) {
            if (tid < 64) {
                *(uint4*)&s.wh[buf ^ 1][srw][sq] = nwh;
                *(uint4*)&s.wl[buf ^ 1][srw][sq] = nwl;
            }
            *(uint4*)&s.ah[buf ^ 1][srw][sq] = nah;
            *(uint4*)&s.al[buf ^ 1][srw][sq] = nal;
        }
        __syncthreads();
        buf ^= 1;
    }
    // stage D into outT [n][o]
    #pragma unroll
    for (int j = 0; j < 2; j++)
        #pragma unroll
        for (int i = 0; i < 2; i++) {
            int nc = wn0 + i * 8 + 2 * t;
            s.outT[nc][j * 16 + g]     = d[j * 2 + i][0];
            s.outT[nc + 1][j * 16 + g] = d[j * 2 + i][1];
            s.outT[nc][j * 16 + g + 8]     = d[j * 2 + i][2];
            s.outT[nc + 1][j * 16 + g + 8] = d[j * 2 + i][3];
        }
    __syncthreads();
}

// ---------------- fused front: weight split + feature split-transpose + neighbor scan + roi ----------------
__global__ void k_front(const float* __restrict__ pts, const float* __restrict__ rois,
                        const float* __restrict__ feat,
                        const float* __restrict__ Wm, const float* __restrict__ W1,
                        const float* __restrict__ W2) {
    __shared__ __align__(16) char sbuf[24576];
    int blk = blockIdx.x;
    if (blk < 227) {
        int id = blk * 256 + threadIdx.x;          // < 58112
        if (id < 32768) {                          // Wf pairs [o][c2]
            int o = id >> 7, c2 = id & 127;
            unsigned lo;
            unsigned hi = pack_split(Wm[o * 259 + 3 + 2 * c2], Wm[o * 259 + 4 + 2 * c2], lo);
            g_Wfh[id] = hi; g_Wfl[id] = lo;
        } else if (id < 33536) {                   // WxT[k][o]
            int t2 = id - 32768; int o = t2 & 255, k = t2 >> 8;
            g_WxT[t2] = Wm[o * 259 + k];
        } else if (id < 49920) {                   // W1 pairs
            int t2 = id - 33536; int o = t2 >> 7, c2 = t2 & 127;
            unsigned lo;
            unsigned hi = pack_split(W1[o * 256 + 2 * c2], W1[o * 256 + 2 * c2 + 1], lo);
            g_W1h[t2] = hi; g_W1l[t2] = lo;
        } else if (id < 58112) {                   // W2 pairs
            int t2 = id - 49920; int o = t2 >> 6, c2 = t2 & 63;
            unsigned lo;
            unsigned hi = pack_split(W2[o * 128 + 2 * c2], W2[o * 128 + 2 * c2 + 1], lo);
            g_W2h[t2] = hi; g_W2l[t2] = lo;
        }
    } else if (blk < 739) {
        // ---- neighbor search: warp-per-point ballot scan ----
        int q = blk - 227;
        int b = q >> 8, chunk = q & 255;
        float* sx = (float*)sbuf;
        float* sy = sx + NN;
        float* sz = sx + 2 * NN;
        const float* P = pts + (size_t)b * NN * 3;
        for (int j = threadIdx.x; j < NN; j += 256) {
            sx[j] = P[j * 3 + 0]; sy[j] = P[j * 3 + 1]; sz[j] = P[j * 3 + 2];
        }
        __syncthreads();
        int warp = threadIdx.x >> 5, lane = threadIdx.x & 31;
        int i = chunk * 8 + warp;
        float xi = sx[i], yi = sy[i], zi = sz[i];
        int base = (b * NN + i) * NSv;
        const float r2 = RADv * RADv;
        int cnt = 0, f0 = -1;
        for (int j0 = 0; j0 < NN; j0 += 32) {
            int j = j0 + lane;
            float dx = sx[j] - xi, dy = sy[j] - yi, dz = sz[j] - zi;
            bool qq = (dx * dx + dy * dy + dz * dz) < r2;
            unsigned m = __ballot_sync(0xffffffffu, qq);
            if (m) {
                if (f0 < 0) f0 = j0 + __ffs(m) - 1;
                int pos = cnt + __popc(m & ((1u << lane) - 1u));
                if (qq && pos < NSv) g_idx[base + pos] = j;
                cnt += __popc(m);
                if (cnt >= NSv) break;
            }
        }
        if (cnt < NSv) {
            for (int s = cnt + lane; s < NSv; s += 32) g_idx[base + s] = f0;
        }
    } else if (blk < 995) {
        // ---- roi point-in-box classify ----
        int br = blk - 739;
        int b = br >> 7;
        int* cnt = (int*)sbuf;
        if (threadIdx.x == 0) *cnt = 0;
        __syncthreads();
        const float* qr = rois + (size_t)br * 7;
        float cx = qr[0], cy = qr[1], cz = qr[2];
        float hx = qr[3] * 0.5f, hy = qr[4] * 0.5f, hz = qr[5] * 0.5f;
        float co = cosf(qr[6]), si = sinf(qr[6]);
        const float* P = pts + (size_t)b * NN * 3;
        int* lst = g_roilst + (size_t)br * NN;
        for (int n = threadIdx.x; n < NN; n += 256) {
            float rx = P[n * 3 + 0] - cx;
            float ry = P[n * 3 + 1] - cy;
            float rz = P[n * 3 + 2] - cz;
            float lx = rx * co + ry * si;
            float ly = -rx * si + ry * co;
            float lz = rz;
            if (fabsf(lx) < hx && fabsf(ly) < hy && fabsf(lz) < hz) {
                int v0 = (int)fminf(fmaxf(floorf((lx + hx) / (2.f * hx) * 5.f), 0.f), 4.f);
                int v1 = (int)fminf(fmaxf(floorf((ly + hy) / (2.f * hy) * 5.f), 0.f), 4.f);
                int v2 = (int)fminf(fmaxf(floorf((lz + hz) / (2.f * hz) * 5.f), 0.f), 4.f);
                int vox = (v0 * 5 + v1) * 5 + v2;
                int pos = atomicAdd(cnt, 1);
                lst[pos] = (vox << 12) | n;
            }
        }
        __syncthreads();
        if (threadIdx.x == 0) g_roicnt[br] = *cnt;
    } else {
        // ---- feature split-transpose: feat[b][c][n] fp32 -> g_Fh/Fl [b][n][c/2] ----
        int q2 = blk - 995;                 // 0..511
        int b = q2 >> 8;
        int rest = q2 & 255;
        int c0 = (rest >> 6) * 64;          // 0,64,128,192
        int n0 = (rest & 63) * 32;
        float* tile = (float*)sbuf;         // [64][33]
        int tx = threadIdx.x & 31, ty = threadIdx.x >> 5;
        #pragma unroll
        for (int r8 = 0; r8 < 8; r8++) {
            int row = r8 * 8 + ty;
            tile[row * 33 + tx] = feat[(size_t)(b * 256 + c0 + row) * NN + n0 + tx];
        }
        __syncthreads();
        int n_l = threadIdx.x >> 3;
        int c2_l = threadIdx.x & 7;
        #pragma unroll
        for (int q = 0; q < 4; q++) {
            int c2 = q * 8 + c2_l;
            unsigned lo;
            unsigned hi = pack_split(tile[(2 * c2) * 33 + n_l], tile[(2 * c2 + 1) * 33 + n_l], lo);
            size_t off = (size_t)(b * NN + n0 + n_l) * 128 + c0 / 2 + c2;
            g_Fh[off] = hi; g_Fl[off] = lo;
        }
    }
}

// ---------------- GEMM G: Gt[b][n][o] = Wf @ feat, pure MMA ----------------
__global__ void k_gemmG() {
    __shared__ SmemGemm s;
    int b = blockIdx.z;
    int n0 = blockIdx.x * 64, o0 = blockIdx.y * 32;
    int tid = threadIdx.x;
    float d[4][4] = {};
    gemm_mainloop<16>(s, g_Wfh, g_Wfl, g_Fh, g_Fl, o0, (size_t)(b * NN + n0), d, tid);
    int n_l = tid >> 1, q = tid & 1;
    float* orow = &g_Gt[(size_t)(b * NN + n0 + n_l) * 256 + o0 + q * 16];
    #pragma unroll
    for (int f = 0; f < 4; f++)
        *(float4*)&orow[f * 4] = *(float4*)&s.outT[n_l][q * 16 + f * 4];
}

// ---------------- gather + xyz MLP + max + BN1 stats (writes hmax [b][n][c]) ----------------
#define PPB 8
__global__ void k_gathermax(const float* __restrict__ pts) {
    __shared__ int   sj[PPB * NSv];
    __shared__ float srx[PPB * NSv], sry[PPB * NSv], srz[PPB * NSv];
    __shared__ float ssum[4][256], ssq[4][256];
    int b = blockIdx.y;
    int n0 = blockIdx.x * PPB;
    int tid = threadIdx.x;
    if (tid < PPB * NSv) {
        int p = tid >> 4, sI = tid & 15;
        int n = n0 + p;
        int j = g_idx[(b * NN + n) * NSv + sI];
        sj[tid] = j;
        const float* P = pts + (size_t)b * NN * 3;
        srx[tid] = (P[j * 3 + 0] - P[n * 3 + 0]) / RADv;
        sry[tid] = (P[j * 3 + 1] - P[n * 3 + 1]) / RADv;
        srz[tid] = (P[j * 3 + 2] - P[n * 3 + 2]) / RADv;
    }
    __syncthreads();
    int co = tid & 63;
    int pg = tid >> 6;
    float4 w0 = *(const float4*)&g_WxT[co * 4];
    float4 w1 = *(const float4*)&g_WxT[256 + co * 4];
    float4 w2 = *(const float4*)&g_WxT[512 + co * 4];
    float4 ls = make_float4(0.f, 0.f, 0.f, 0.f);
    float4 lq = make_float4(0.f, 0.f, 0.f, 0.f);
    const float* Gb = g_Gt + (size_t)b * NN * 256;
    #pragma unroll
    for (int pp = 0; pp < 2; pp++) {
        int p = pg * 2 + pp;
        float4 m = make_float4(-3.4e38f, -3.4e38f, -3.4e38f, -3.4e38f);
        #pragma unroll
        for (int sI = 0; sI < NSv; sI++) {
            int e = p * NSv + sI;
            int j = sj[e];
            float rx = srx[e], ry = sry[e], rz = srz[e];
            float4 gv = *(const float4*)&Gb[(size_t)j * 256 + co * 4];
            float4 v;
            v.x = gv.x + w0.x * rx + w1.x * ry + w2.x * rz;
            v.y = gv.y + w0.y * rx + w1.y * ry + w2.y * rz;
            v.z = gv.z + w0.z * rx + w1.z * ry + w2.z * rz;
            v.w = gv.w + w0.w * rx + w1.w * ry + w2.w * rz;
            m.x = fmaxf(m.x, v.x); m.y = fmaxf(m.y, v.y);
            m.z = fmaxf(m.z, v.z); m.w = fmaxf(m.w, v.w);
            ls.x += v.x; ls.y += v.y; ls.z += v.z; ls.w += v.w;
            lq.x += v.x * v.x; lq.y += v.y * v.y; lq.z += v.z * v.z; lq.w += v.w * v.w;
        }
        *(float4*)&g_hmax[(size_t)(b * NN + n0 + p) * 256 + co * 4] = m;
    }
    ssum[pg][co * 4 + 0] = ls.x; ssum[pg][co * 4 + 1] = ls.y;
    ssum[pg][co * 4 + 2] = ls.z; ssum[pg][co * 4 + 3] = ls.w;
    ssq[pg][co * 4 + 0] = lq.x; ssq[pg][co * 4 + 1] = lq.y;
    ssq[pg][co * 4 + 2] = lq.z; ssq[pg][co * 4 + 3] = lq.w;
    __syncthreads();
    float ts = ssum[0][tid] + ssum[1][tid] + ssum[2][tid] + ssum[3][tid];
    float tq = ssq[0][tid] + ssq[1][tid] + ssq[2][tid] + ssq[3][tid];
    atomicAdd(&g_stats[tid], ts);
    atomicAdd(&g_stats[256 + tid], tq);
}

// ---------------- conv1: relu(bn1(hmax)) -> split bf16 [b][n][128] ----------------
__global__ void k_conv1(const float* __restrict__ gm, const float* __restrict__ btm) {
    __shared__ float ssc[256], ssh[256];
    int tid = threadIdx.x;
    {
        float m = g_stats[tid] * (1.f / 65536.f);
        float v = g_stats[256 + tid] * (1.f / 65536.f) - m * m;
        float sc = gm[tid] * rsqrtf(v + EPSv);
        ssc[tid] = sc; ssh[tid] = btm[tid] - m * sc;
    }
    __syncthreads();
    int bn = blockIdx.x * 4 + (tid >> 6);
    int c4 = (tid & 63) * 4;
    float4 v = *(const float4*)&g_hmax[(size_t)bn * 256 + c4];
    float x0 = fmaxf(v.x * ssc[c4] + ssh[c4], 0.f);
    float x1 = fmaxf(v.y * ssc[c4 + 1] + ssh[c4 + 1], 0.f);
    float x2 = fmaxf(v.z * ssc[c4 + 2] + ssh[c4 + 2], 0.f);
    float x3 = fmaxf(v.w * ssc[c4 + 3] + ssh[c4 + 3], 0.f);
    unsigned lo0, lo1;
    unsigned hi0 = pack_split(x0, x1, lo0);
    unsigned hi1 = pack_split(x2, x3, lo1);
    *(uint2*)&g_A1h[(size_t)bn * 128 + c4 / 2] = make_uint2(hi0, hi1);
    *(uint2*)&g_A1l[(size_t)bn * 128 + c4 / 2] = make_uint2(lo0, lo1);
}

// ---------------- GEMM1: h2[b][n][o] = b1 + W1 @ A1, fused BN2 stats ----------------
__global__ void k_gemm1(const float* __restrict__ b1) {
    __shared__ SmemGemm s;
    int b = blockIdx.z;
    int n0 = blockIdx.x * 64, o0 = blockIdx.y * 32;
    int tid = threadIdx.x;
    float d[4][4] = {};
    gemm_mainloop<16>(s, g_W1h, g_W1l, g_A1h, g_A1l, o0, (size_t)(b * NN + n0), d, tid);
    int o_l = tid & 31, chunk = tid >> 5;
    int o = o0 + o_l;
    float bias = b1[o];
    float sum = 0.f, sq = 0.f;
    #pragma unroll
    for (int r = 0; r < 16; r++) {
        int n = chunk * 16 + r;
        float v = s.outT[n][o_l] + bias;
        sum += v; sq += v * v;
        g_h2[(size_t)(b * NN + n0 + n) * C1v + o] = v;
    }
    atomicAdd(&g_stats[512 + o], sum);
    atomicAdd(&g_stats[640 + o], sq);
}

// ---------------- conv2: relu(bn2(h2)) -> split bf16 [b][n][64] ----------------
__global__ void k_conv2(const float* __restrict__ g1, const float* __restrict__ bt1) {
    __shared__ float ssc[128], ssh[128];
    int tid = threadIdx.x;
    if (tid < 128) {
        float m = g_stats[512 + tid] * (1.f / 4096.f);
        float v = g_stats[640 + tid] * (1.f / 4096.f) - m * m;
        float sc = g1[tid] * rsqrtf(v + EPSv);
        ssc[tid] = sc; ssh[tid] = bt1[tid] - m * sc;
    }
    __syncthreads();
    int bn = blockIdx.x * 8 + (tid >> 5);
    int c4 = (tid & 31) * 4;
    float4 v = *(const float4*)&g_h2[(size_t)bn * 128 + c4];
    float x0 = fmaxf(v.x * ssc[c4] + ssh[c4], 0.f);
    float x1 = fmaxf(v.y * ssc[c4 + 1] + ssh[c4 + 1], 0.f);
    float x2 = fmaxf(v.z * ssc[c4 + 2] + ssh[c4 + 2], 0.f);
    float x3 = fmaxf(v.w * ssc[c4 + 3] + ssh[c4 + 3], 0.f);
    unsigned lo0, lo1;
    unsigned hi0 = pack_split(x0, x1, lo0);
    unsigned hi1 = pack_split(x2, x3, lo1);
    *(uint2*)&g_A2h[(size_t)bn * 64 + c4 / 2] = make_uint2(hi0, hi1);
    *(uint2*)&g_A2l[(size_t)bn * 64 + c4 / 2] = make_uint2(lo0, lo1);
}

// ---------------- GEMM2: h3[b][n][o] = b2 + W2 @ A2, fused BN3 stats ----------------
__global__ void k_gemm2(const float* __restrict__ b2) {
    __shared__ SmemGemm s;
    int b = blockIdx.z;
    int n0 = blockIdx.x * 64, o0 = blockIdx.y * 32;
    int tid = threadIdx.x;
    float d[4][4] = {};
    gemm_mainloop<8>(s, g_W2h, g_W2l, g_A2h, g_A2l, o0, (size_t)(b * NN + n0), d, tid);
    int o_l = tid & 31, chunk = tid >> 5;
    int o = o0 + o_l;
    float bias = b2[o];
    float sum = 0.f, sq = 0.f;
    #pragma unroll
    for (int r = 0; r < 16; r++) {
        int n = chunk * 16 + r;
        float v = s.outT[n][o_l] + bias;
        sum += v; sq += v * v;
        g_h3[(size_t)(b * NN + n0 + n) * C1v + o] = v;
    }
    atomicAdd(&g_stats[768 + o], sum);
    atomicAdd(&g_stats[896 + o], sq);
}

// ---------------- final feats: BN3+ReLU; write featsT [n][c] direct + out [c][n] transposed ----------------
__global__ void k_feats(const float* __restrict__ g2, const float* __restrict__ bt2,
                        float* __restrict__ out) {
    __shared__ float t[32][33];
    __shared__ float ssc[32], ssh[32];
    int b = blockIdx.z;
    int n0 = blockIdx.x * 32, o0 = blockIdx.y * 32;
    int tid = threadIdx.x;
    int tx = tid & 31, ty = tid >> 5;          // 32x8
    if (tid < 32) {
        int o = o0 + tid;
        float m = g_stats[768 + o] * (1.f / 4096.f);
        float v = g_stats[896 + o] * (1.f / 4096.f) - m * m;
        float sc = g2[o] * rsqrtf(v + EPSv);
        ssc[tid] = sc; ssh[tid] = bt2[o] - m * sc;
    }
    __syncthreads();
    #pragma unroll
    for (int r = 0; r < 4; r++) {
        int n_l = ty + r * 8;
        size_t e = (size_t)(b * NN + n0 + n_l) * C1v + o0 + tx;
        float f = fmaxf(g_h3[e] * ssc[tx] + ssh[tx], 0.f);
        g_featsT[e] = f;
        t[n_l][tx] = f;
    }
    __syncthreads();
    #pragma unroll
    for (int r = 0; r < 4; r++) {
        int o_l = ty + r * 8;
        out[(size_t)(b * C1v + o0 + o_l) * NN + n0 + tx] = t[tx][o_l];
    }
}

// ---------------- RoI voxel max-pool ----------------
__global__ void k_roipool(float* __restrict__ out) {
    extern __shared__ float sg[];            // 125*128 floats
    int br = blockIdx.x;
    int b = br >> 7;
    int t = threadIdx.x;                     // 512
    for (int i = t; i < 125 * C1v / 4; i += 512)
        ((float4*)sg)[i] = make_float4(0.f, 0.f, 0.f, 0.f);
    __syncthreads();
    const float* F = g_featsT + (size_t)b * NN * C1v;
    const int* lst = g_roilst + (size_t)br * NN;
    int m = g_roicnt[br];
    int ch = t & 127;
    int slot = t >> 7;
    for (int e = slot; e < m; e += 4) {
        int pk = lst[e];
        int n = pk & 4095;
        int vox = pk >> 12;
        float val = F[(size_t)n * C1v + ch];
        atomicMax((int*)&sg[vox * C1v + ch], __float_as_int(val));
    }
    __syncthreads();
    float4* og = (float4*)(out + FEATS_SZ + (size_t)br * 125 * C1v);
    for (int i = t; i < 125 * C1v / 4; i += 512) og[i] = ((float4*)sg)[i];
}

// ---------------- launch ----------------
extern "C" void kernel_launch(void* const* d_in, const int* in_sizes, int n_in,
                              void* d_out, int out_size) {
    const float* pts    = (const float*)d_in[0];
    const float* feat   = (const float*)d_in[1];
    const float* rois   = (const float*)d_in[2];
    const float* W_mlp  = (const float*)d_in[3];
    const float* g_mlp  = (const float*)d_in[4];
    const float* btm    = (const float*)d_in[5];
    const float* W1     = (const float*)d_in[6];
    const float* b1     = (const float*)d_in[7];
    const float* g1     = (const float*)d_in[8];
    const float* bt1    = (const float*)d_in[9];
    const float* W2     = (const float*)d_in[10];
    const float* b2     = (const float*)d_in[11];
    const float* g2     = (const float*)d_in[12];
    const float* bt2    = (const float*)d_in[13];
    float* out = (float*)d_out;

    cudaFuncSetAttribute(k_roipool, cudaFuncAttributeMaxDynamicSharedMemorySize,
                         125 * C1v * sizeof(float));

    void* statsPtr = nullptr;
    cudaGetSymbolAddress(&statsPtr, g_stats);
    cudaMemsetAsync(statsPtr, 0, 1024 * sizeof(float), 0);

    k_front<<<1507, 256>>>(pts, rois, feat, W_mlp, W1, W2);
    k_gemmG<<<dim3(NN / 64, 256 / 32, BB), 128>>>();
    k_gathermax<<<dim3(NN / PPB, BB), 256>>>(pts);
    k_conv1<<<BB * NN / 4, 256>>>(g_mlp, btm);
    k_gemm1<<<dim3(NN / 64, C1v / 32, BB), 128>>>(b1);
    k_conv2<<<BB * NN / 8, 256>>>(g1, bt1);
    k_gemm2<<<dim3(NN / 64, C1v / 32, BB), 128>>>(b2);
    k_feats<<<dim3(NN / 32, C1v / 32, BB), 256>>>(g2, bt2, out);
    k_roipool<<<BB * RRoi, 512, 125 * C1v * sizeof(float)>>>(out);
}

// round 10
// speedup vs baseline: 1.1010x; 1.0425x over previous
#include <cuda_runtime.h>
#include <cuda_bf16.h>
#include <math.h>

// Problem constants
#define BB   2
#define NN   2048
#define RRoi 128
#define CINv 256
#define NSv  16
#define C1v  128
#define RADv 0.3f
#define EPSv 1e-5f
#define FEATS_SZ (BB*C1v*NN)          // 524288
#define GRID_SZ  (BB*RRoi*125*C1v)    // 4096000

// ---------------- scratch ----------------
__device__ int   g_idx[BB*NN*NSv];
__device__ float g_Gt[BB*NN*256];        // [b][n][o]  (o contiguous)
__device__ float g_hmax[BB*NN*256];      // [b][n][c]  (c contiguous)
__device__ float g_h2[BB*NN*C1v];        // [b][n][o]
__device__ float g_h3[BB*NN*C1v];        // [b][n][o]
__device__ float g_WxT[3*256];           // [k][o]
// packed bf16x2, hi/lo split. weights [o][k/2]; activations [b][n][k/2]
__device__ unsigned g_Wfh[256*128], g_Wfl[256*128];
__device__ unsigned g_W1h[128*128], g_W1l[128*128];
__device__ unsigned g_W2h[128*64],  g_W2l[128*64];
__device__ unsigned g_Fh[BB*NN*128],  g_Fl[BB*NN*128];   // split features
__device__ unsigned g_A1h[BB*NN*128], g_A1l[BB*NN*128];  // split relu(bn1(hmax))
__device__ unsigned g_A2h[BB*NN*64],  g_A2l[BB*NN*64];   // split relu(bn2(h2))
__device__ int   g_roilst[BB*RRoi*NN];
__device__ int   g_roicnt[BB*RRoi];
// stats: [0:256) sum1 [256:512) sq1 [512:640) sum2 [640:768) sq2 [768:896) sum3 [896:1024) sq3
__device__ float g_stats[1024];

// ---------------- helpers ----------------
__device__ __forceinline__ unsigned pack_split(float x0, float x1, unsigned& lo) {
    __nv_bfloat16 h0 = __float2bfloat16(x0);
    __nv_bfloat16 h1 = __float2bfloat16(x1);
    __nv_bfloat16 l0 = __float2bfloat16(x0 - __bfloat162float(h0));
    __nv_bfloat16 l1 = __float2bfloat16(x1 - __bfloat162float(h1));
    lo = ((unsigned)__bfloat16_as_ushort(l1) << 16) | (unsigned)__bfloat16_as_ushort(l0);
    return ((unsigned)__bfloat16_as_ushort(h1) << 16) | (unsigned)__bfloat16_as_ushort(h0);
}

__device__ __forceinline__ void mma16816(float* d, const unsigned* a, const unsigned* b) {
    asm volatile(
        "mma.sync.aligned.m16n8k16.row.col.f32.bf16.bf16.f32 "
        "{%0,%1,%2,%3}, {%4,%5,%6,%7}, {%8,%9}, {%0,%1,%2,%3};"
        : "+f"(d[0]), "+f"(d[1]), "+f"(d[2]), "+f"(d[3])
        : "r"(a[0]), "r"(a[1]), "r"(a[2]), "r"(a[3]), "r"(b[0]), "r"(b[1]));
}

struct SmemGemm {
    unsigned wh[2][32][12], wl[2][32][12];
    unsigned ah[2][64][12], al[2][64][12];
    float outT[64][36];
};

// pure-MMA mainloop: 32o x 64n tile, 128 threads, pre-split operands in global.
// d is a flat [4][4] accumulator array: d[j*2+i] = (o-half j, n-half i).
template<int KSTEPS>
__device__ __forceinline__ void gemm_mainloop(
    SmemGemm& s,
    const unsigned* __restrict__ Wh, const unsigned* __restrict__ Wl,
    const unsigned* __restrict__ Ah, const unsigned* __restrict__ Al,
    int o0, size_t nbase, float (*d)[4], int tid)
{
    const int kw2 = KSTEPS * 8;
    int lane = tid & 31, warp = tid >> 5;
    int g = lane >> 2, t = lane & 3;
    int wn0 = warp * 16;
    int srw = tid >> 1;            // 0..63 (weights use tid<64 -> 0..31)
    int sq = (tid & 1) * 4;
    // prologue: fill buf 0
    if (tid < 64) {
        *(uint4*)&s.wh[0][srw][sq] = *(const uint4*)&Wh[(size_t)(o0 + srw) * kw2 + sq];
        *(uint4*)&s.wl[0][srw][sq] = *(const uint4*)&Wl[(size_t)(o0 + srw) * kw2 + sq];
    }
    *(uint4*)&s.ah[0][srw][sq] = *(const uint4*)&Ah[(nbase + srw) * kw2 + sq];
    *(uint4*)&s.al[0][srw][sq] = *(const uint4*)&Al[(nbase + srw) * kw2 + sq];
    __syncthreads();
    int buf = 0;
    #pragma unroll
    for (int ks = 0; ks < KSTEPS; ks++) {
        uint4 nwh, nwl, nah, nal;
        if (ks + 1 < KSTEPS) {
            int kw = (ks + 1) * 8 + sq;
            if (tid < 64) {
                nwh = *(const uint4*)&Wh[(size_t)(o0 + srw) * kw2 + kw];
                nwl = *(const uint4*)&Wl[(size_t)(o0 + srw) * kw2 + kw];
            }
            nah = *(const uint4*)&Ah[(nbase + srw) * kw2 + kw];
            nal = *(const uint4*)&Al[(nbase + srw) * kw2 + kw];
        }
        unsigned whf[2][4], wlf[2][4], bhf[2][2], blf[2][2];
        #pragma unroll
        for (int j = 0; j < 2; j++) {
            int r0 = j * 16 + g;
            whf[j][0] = s.wh[buf][r0][t];     whf[j][1] = s.wh[buf][r0 + 8][t];
            whf[j][2] = s.wh[buf][r0][t + 4]; whf[j][3] = s.wh[buf][r0 + 8][t + 4];
            wlf[j][0] = s.wl[buf][r0][t];     wlf[j][1] = s.wl[buf][r0 + 8][t];
            wlf[j][2] = s.wl[buf][r0][t + 4]; wlf[j][3] = s.wl[buf][r0 + 8][t + 4];
        }
        #pragma unroll
        for (int i = 0; i < 2; i++) {
            int n = wn0 + i * 8 + g;
            bhf[i][0] = s.ah[buf][n][t]; bhf[i][1] = s.ah[buf][n][t + 4];
            blf[i][0] = s.al[buf][n][t]; blf[i][1] = s.al[buf][n][t + 4];
        }
        #pragma unroll
        for (int j = 0; j < 2; j++)
            #pragma unroll
            for (int i = 0; i < 2; i++) {
                mma16816(d[j * 2 + i], whf[j], bhf[i]);
                mma16816(d[j * 2 + i], whf[j], blf[i]);
                mma16816(d[j * 2 + i], wlf[j], bhf[i]);
            }
        if (ks + 1 < KSTEPS) {
            if (tid < 64) {
                *(uint4*)&s.wh[buf ^ 1][srw][sq] = nwh;
                *(uint4*)&s.wl[buf ^ 1][srw][sq] = nwl;
            }
            *(uint4*)&s.ah[buf ^ 1][srw][sq] = nah;
            *(uint4*)&s.al[buf ^ 1][srw][sq] = nal;
        }
        __syncthreads();
        buf ^= 1;
    }
    // stage D into outT [n][o]
    #pragma unroll
    for (int j = 0; j < 2; j++)
        #pragma unroll
        for (int i = 0; i < 2; i++) {
            int nc = wn0 + i * 8 + 2 * t;
            s.outT[nc][j * 16 + g]     = d[j * 2 + i][0];
            s.outT[nc + 1][j * 16 + g] = d[j * 2 + i][1];
            s.outT[nc][j * 16 + g + 8]     = d[j * 2 + i][2];
            s.outT[nc + 1][j * 16 + g + 8] = d[j * 2 + i][3];
        }
    __syncthreads();
}

// ---------------- fused front: weight split + feature split-transpose + neighbor scan + roi + stats zero ----------------
__global__ void k_front(const float* __restrict__ pts, const float* __restrict__ rois,
                        const float* __restrict__ feat,
                        const float* __restrict__ Wm, const float* __restrict__ W1,
                        const float* __restrict__ W2) {
    __shared__ __align__(16) char sbuf[24576];
    int blk = blockIdx.x;
    if (blk < 227) {
        if (blk == 0) {
            for (int i = threadIdx.x; i < 1024; i += 256) g_stats[i] = 0.f;
        }
        int id = blk * 256 + threadIdx.x;          // < 58112
        if (id < 32768) {                          // Wf pairs [o][c2]
            int o = id >> 7, c2 = id & 127;
            unsigned lo;
            unsigned hi = pack_split(Wm[o * 259 + 3 + 2 * c2], Wm[o * 259 + 4 + 2 * c2], lo);
            g_Wfh[id] = hi; g_Wfl[id] = lo;
        } else if (id < 33536) {                   // WxT[k][o]
            int t2 = id - 32768; int o = t2 & 255, k = t2 >> 8;
            g_WxT[t2] = Wm[o * 259 + k];
        } else if (id < 49920) {                   // W1 pairs
            int t2 = id - 33536; int o = t2 >> 7, c2 = t2 & 127;
            unsigned lo;
            unsigned hi = pack_split(W1[o * 256 + 2 * c2], W1[o * 256 + 2 * c2 + 1], lo);
            g_W1h[t2] = hi; g_W1l[t2] = lo;
        } else if (id < 58112) {                   // W2 pairs
            int t2 = id - 49920; int o = t2 >> 6, c2 = t2 & 63;
            unsigned lo;
            unsigned hi = pack_split(W2[o * 128 + 2 * c2], W2[o * 128 + 2 * c2 + 1], lo);
            g_W2h[t2] = hi; g_W2l[t2] = lo;
        }
    } else if (blk < 739) {
        // ---- neighbor search: warp-per-point ballot scan ----
        int q = blk - 227;
        int b = q >> 8, chunk = q & 255;
        float* sx = (float*)sbuf;
        float* sy = sx + NN;
        float* sz = sx + 2 * NN;
        const float* P = pts + (size_t)b * NN * 3;
        for (int j = threadIdx.x; j < NN; j += 256) {
            sx[j] = P[j * 3 + 0]; sy[j] = P[j * 3 + 1]; sz[j] = P[j * 3 + 2];
        }
        __syncthreads();
        int warp = threadIdx.x >> 5, lane = threadIdx.x & 31;
        int i = chunk * 8 + warp;
        float xi = sx[i], yi = sy[i], zi = sz[i];
        int base = (b * NN + i) * NSv;
        const float r2 = RADv * RADv;
        int cnt = 0, f0 = -1;
        for (int j0 = 0; j0 < NN; j0 += 32) {
            int j = j0 + lane;
            float dx = sx[j] - xi, dy = sy[j] - yi, dz = sz[j] - zi;
            bool qq = (dx * dx + dy * dy + dz * dz) < r2;
            unsigned m = __ballot_sync(0xffffffffu, qq);
            if (m) {
                if (f0 < 0) f0 = j0 + __ffs(m) - 1;
                int pos = cnt + __popc(m & ((1u << lane) - 1u));
                if (qq && pos < NSv) g_idx[base + pos] = j;
                cnt += __popc(m);
                if (cnt >= NSv) break;
            }
        }
        if (cnt < NSv) {
            for (int s = cnt + lane; s < NSv; s += 32) g_idx[base + s] = f0;
        }
    } else if (blk < 995) {
        // ---- roi point-in-box classify ----
        int br = blk - 739;
        int b = br >> 7;
        int* cnt = (int*)sbuf;
        if (threadIdx.x == 0) *cnt = 0;
        __syncthreads();
        const float* qr = rois + (size_t)br * 7;
        float cx = qr[0], cy = qr[1], cz = qr[2];
        float hx = qr[3] * 0.5f, hy = qr[4] * 0.5f, hz = qr[5] * 0.5f;
        float co = cosf(qr[6]), si = sinf(qr[6]);
        const float* P = pts + (size_t)b * NN * 3;
        int* lst = g_roilst + (size_t)br * NN;
        for (int n = threadIdx.x; n < NN; n += 256) {
            float rx = P[n * 3 + 0] - cx;
            float ry = P[n * 3 + 1] - cy;
            float rz = P[n * 3 + 2] - cz;
            float lx = rx * co + ry * si;
            float ly = -rx * si + ry * co;
            float lz = rz;
            if (fabsf(lx) < hx && fabsf(ly) < hy && fabsf(lz) < hz) {
                int v0 = (int)fminf(fmaxf(floorf((lx + hx) / (2.f * hx) * 5.f), 0.f), 4.f);
                int v1 = (int)fminf(fmaxf(floorf((ly + hy) / (2.f * hy) * 5.f), 0.f), 4.f);
                int v2 = (int)fminf(fmaxf(floorf((lz + hz) / (2.f * hz) * 5.f), 0.f), 4.f);
                int vox = (v0 * 5 + v1) * 5 + v2;
                int pos = atomicAdd(cnt, 1);
                lst[pos] = (vox << 12) | n;
            }
        }
        __syncthreads();
        if (threadIdx.x == 0) g_roicnt[br] = *cnt;
    } else {
        // ---- feature split-transpose: feat[b][c][n] fp32 -> g_Fh/Fl [b][n][c/2] ----
        int q2 = blk - 995;                 // 0..511
        int b = q2 >> 8;
        int rest = q2 & 255;
        int c0 = (rest >> 6) * 64;          // 0,64,128,192
        int n0 = (rest & 63) * 32;
        float* tile = (float*)sbuf;         // [64][33]
        int tx = threadIdx.x & 31, ty = threadIdx.x >> 5;
        #pragma unroll
        for (int r8 = 0; r8 < 8; r8++) {
            int row = r8 * 8 + ty;
            tile[row * 33 + tx] = feat[(size_t)(b * 256 + c0 + row) * NN + n0 + tx];
        }
        __syncthreads();
        int n_l = threadIdx.x >> 3;
        int c2_l = threadIdx.x & 7;
        #pragma unroll
        for (int q = 0; q < 4; q++) {
            int c2 = q * 8 + c2_l;
            unsigned lo;
            unsigned hi = pack_split(tile[(2 * c2) * 33 + n_l], tile[(2 * c2 + 1) * 33 + n_l], lo);
            size_t off = (size_t)(b * NN + n0 + n_l) * 128 + c0 / 2 + c2;
            g_Fh[off] = hi; g_Fl[off] = lo;
        }
    }
}

// ---------------- GEMM G: Gt[b][n][o] = Wf @ feat, pure MMA ----------------
__global__ void k_gemmG() {
    __shared__ SmemGemm s;
    int b = blockIdx.z;
    int n0 = blockIdx.x * 64, o0 = blockIdx.y * 32;
    int tid = threadIdx.x;
    float d[4][4] = {};
    gemm_mainloop<16>(s, g_Wfh, g_Wfl, g_Fh, g_Fl, o0, (size_t)(b * NN + n0), d, tid);
    int n_l = tid >> 1, q = tid & 1;
    float* orow = &g_Gt[(size_t)(b * NN + n0 + n_l) * 256 + o0 + q * 16];
    #pragma unroll
    for (int f = 0; f < 4; f++)
        *(float4*)&orow[f * 4] = *(float4*)&s.outT[n_l][q * 16 + f * 4];
}

// ---------------- gather + xyz MLP + max + BN1 stats (writes hmax [b][n][c]) ----------------
#define PPB 8
__global__ void k_gathermax(const float* __restrict__ pts) {
    __shared__ int   sj[PPB * NSv];
    __shared__ float srx[PPB * NSv], sry[PPB * NSv], srz[PPB * NSv];
    __shared__ float ssum[4][256], ssq[4][256];
    int b = blockIdx.y;
    int n0 = blockIdx.x * PPB;
    int tid = threadIdx.x;
    if (tid < PPB * NSv) {
        int p = tid >> 4, sI = tid & 15;
        int n = n0 + p;
        int j = g_idx[(b * NN + n) * NSv + sI];
        sj[tid] = j;
        const float* P = pts + (size_t)b * NN * 3;
        srx[tid] = (P[j * 3 + 0] - P[n * 3 + 0]) / RADv;
        sry[tid] = (P[j * 3 + 1] - P[n * 3 + 1]) / RADv;
        srz[tid] = (P[j * 3 + 2] - P[n * 3 + 2]) / RADv;
    }
    __syncthreads();
    int co = tid & 63;
    int pg = tid >> 6;
    float4 w0 = *(const float4*)&g_WxT[co * 4];
    float4 w1 = *(const float4*)&g_WxT[256 + co * 4];
    float4 w2 = *(const float4*)&g_WxT[512 + co * 4];
    float4 ls = make_float4(0.f, 0.f, 0.f, 0.f);
    float4 lq = make_float4(0.f, 0.f, 0.f, 0.f);
    const float* Gb = g_Gt + (size_t)b * NN * 256;
    #pragma unroll
    for (int pp = 0; pp < 2; pp++) {
        int p = pg * 2 + pp;
        float4 m = make_float4(-3.4e38f, -3.4e38f, -3.4e38f, -3.4e38f);
        #pragma unroll
        for (int sI = 0; sI < NSv; sI++) {
            int e = p * NSv + sI;
            int j = sj[e];
            float rx = srx[e], ry = sry[e], rz = srz[e];
            float4 gv = *(const float4*)&Gb[(size_t)j * 256 + co * 4];
            float4 v;
            v.x = gv.x + w0.x * rx + w1.x * ry + w2.x * rz;
            v.y = gv.y + w0.y * rx + w1.y * ry + w2.y * rz;
            v.z = gv.z + w0.z * rx + w1.z * ry + w2.z * rz;
            v.w = gv.w + w0.w * rx + w1.w * ry + w2.w * rz;
            m.x = fmaxf(m.x, v.x); m.y = fmaxf(m.y, v.y);
            m.z = fmaxf(m.z, v.z); m.w = fmaxf(m.w, v.w);
            ls.x += v.x; ls.y += v.y; ls.z += v.z; ls.w += v.w;
            lq.x += v.x * v.x; lq.y += v.y * v.y; lq.z += v.z * v.z; lq.w += v.w * v.w;
        }
        *(float4*)&g_hmax[(size_t)(b * NN + n0 + p) * 256 + co * 4] = m;
    }
    ssum[pg][co * 4 + 0] = ls.x; ssum[pg][co * 4 + 1] = ls.y;
    ssum[pg][co * 4 + 2] = ls.z; ssum[pg][co * 4 + 3] = ls.w;
    ssq[pg][co * 4 + 0] = lq.x; ssq[pg][co * 4 + 1] = lq.y;
    ssq[pg][co * 4 + 2] = lq.z; ssq[pg][co * 4 + 3] = lq.w;
    __syncthreads();
    float ts = ssum[0][tid] + ssum[1][tid] + ssum[2][tid] + ssum[3][tid];
    float tq = ssq[0][tid] + ssq[1][tid] + ssq[2][tid] + ssq[3][tid];
    atomicAdd(&g_stats[tid], ts);
    atomicAdd(&g_stats[256 + tid], tq);
}

// ---------------- conv1: relu(bn1(hmax)) -> split bf16 [b][n][128], 4 rows/thread ----------------
__global__ void k_conv1(const float* __restrict__ gm, const float* __restrict__ btm) {
    __shared__ float ssc[256], ssh[256];
    int tid = threadIdx.x;
    {
        float m = g_stats[tid] * (1.f / 65536.f);
        float v = g_stats[256 + tid] * (1.f / 65536.f) - m * m;
        float sc = gm[tid] * rsqrtf(v + EPSv);
        ssc[tid] = sc; ssh[tid] = btm[tid] - m * sc;
    }
    __syncthreads();
    int base = blockIdx.x * 16 + (tid >> 6);     // rows base, base+4, base+8, base+12
    int c4 = (tid & 63) * 4;
    float sc0 = ssc[c4], sc1 = ssc[c4 + 1], sc2 = ssc[c4 + 2], sc3 = ssc[c4 + 3];
    float sh0 = ssh[c4], sh1 = ssh[c4 + 1], sh2 = ssh[c4 + 2], sh3 = ssh[c4 + 3];
    float4 v[4];
    #pragma unroll
    for (int i = 0; i < 4; i++)
        v[i] = *(const float4*)&g_hmax[(size_t)(base + i * 4) * 256 + c4];
    #pragma unroll
    for (int i = 0; i < 4; i++) {
        float x0 = fmaxf(v[i].x * sc0 + sh0, 0.f);
        float x1 = fmaxf(v[i].y * sc1 + sh1, 0.f);
        float x2 = fmaxf(v[i].z * sc2 + sh2, 0.f);
        float x3 = fmaxf(v[i].w * sc3 + sh3, 0.f);
        unsigned lo0, lo1;
        unsigned hi0 = pack_split(x0, x1, lo0);
        unsigned hi1 = pack_split(x2, x3, lo1);
        size_t bn = (size_t)(base + i * 4);
        *(uint2*)&g_A1h[bn * 128 + c4 / 2] = make_uint2(hi0, hi1);
        *(uint2*)&g_A1l[bn * 128 + c4 / 2] = make_uint2(lo0, lo1);
    }
}

// ---------------- GEMM1: h2[b][n][o] = b1 + W1 @ A1, fused BN2 stats ----------------
__global__ void k_gemm1(const float* __restrict__ b1) {
    __shared__ SmemGemm s;
    int b = blockIdx.z;
    int n0 = blockIdx.x * 64, o0 = blockIdx.y * 32;
    int tid = threadIdx.x;
    float d[4][4] = {};
    gemm_mainloop<16>(s, g_W1h, g_W1l, g_A1h, g_A1l, o0, (size_t)(b * NN + n0), d, tid);
    int o_l = tid & 31, chunk = tid >> 5;
    int o = o0 + o_l;
    float bias = b1[o];
    float sum = 0.f, sq = 0.f;
    #pragma unroll
    for (int r = 0; r < 16; r++) {
        int n = chunk * 16 + r;
        float v = s.outT[n][o_l] + bias;
        sum += v; sq += v * v;
        g_h2[(size_t)(b * NN + n0 + n) * C1v + o] = v;
    }
    atomicAdd(&g_stats[512 + o], sum);
    atomicAdd(&g_stats[640 + o], sq);
}

// ---------------- conv2: relu(bn2(h2)) -> split bf16 [b][n][64], 4 rows/thread ----------------
__global__ void k_conv2(const float* __restrict__ g1, const float* __restrict__ bt1) {
    __shared__ float ssc[128], ssh[128];
    int tid = threadIdx.x;
    if (tid < 128) {
        float m = g_stats[512 + tid] * (1.f / 4096.f);
        float v = g_stats[640 + tid] * (1.f / 4096.f) - m * m;
        float sc = g1[tid] * rsqrtf(v + EPSv);
        ssc[tid] = sc; ssh[tid] = bt1[tid] - m * sc;
    }
    __syncthreads();
    int base = blockIdx.x * 32 + (tid >> 5);     // rows base, base+8, base+16, base+24
    int c4 = (tid & 31) * 4;
    float sc0 = ssc[c4], sc1 = ssc[c4 + 1], sc2 = ssc[c4 + 2], sc3 = ssc[c4 + 3];
    float sh0 = ssh[c4], sh1 = ssh[c4 + 1], sh2 = ssh[c4 + 2], sh3 = ssh[c4 + 3];
    float4 v[4];
    #pragma unroll
    for (int i = 0; i < 4; i++)
        v[i] = *(const float4*)&g_h2[(size_t)(base + i * 8) * 128 + c4];
    #pragma unroll
    for (int i = 0; i < 4; i++) {
        float x0 = fmaxf(v[i].x * sc0 + sh0, 0.f);
        float x1 = fmaxf(v[i].y * sc1 + sh1, 0.f);
        float x2 = fmaxf(v[i].z * sc2 + sh2, 0.f);
        float x3 = fmaxf(v[i].w * sc3 + sh3, 0.f);
        unsigned lo0, lo1;
        unsigned hi0 = pack_split(x0, x1, lo0);
        unsigned hi1 = pack_split(x2, x3, lo1);
        size_t bn = (size_t)(base + i * 8);
        *(uint2*)&g_A2h[bn * 64 + c4 / 2] = make_uint2(hi0, hi1);
        *(uint2*)&g_A2l[bn * 64 + c4 / 2] = make_uint2(lo0, lo1);
    }
}

// ---------------- GEMM2: h3[b][n][o] = b2 + W2 @ A2, fused BN3 stats ----------------
__global__ void k_gemm2(const float* __restrict__ b2) {
    __shared__ SmemGemm s;
    int b = blockIdx.z;
    int n0 = blockIdx.x * 64, o0 = blockIdx.y * 32;
    int tid = threadIdx.x;
    float d[4][4] = {};
    gemm_mainloop<8>(s, g_W2h, g_W2l, g_A2h, g_A2l, o0, (size_t)(b * NN + n0), d, tid);
    int o_l = tid & 31, chunk = tid >> 5;
    int o = o0 + o_l;
    float bias = b2[o];
    float sum = 0.f, sq = 0.f;
    #pragma unroll
    for (int r = 0; r < 16; r++) {
        int n = chunk * 16 + r;
        float v = s.outT[n][o_l] + bias;
        sum += v; sq += v * v;
        g_h3[(size_t)(b * NN + n0 + n) * C1v + o] = v;
    }
    atomicAdd(&g_stats[768 + o], sum);
    atomicAdd(&g_stats[896 + o], sq);
}

// ---------------- final: roipool (inline BN3 from h3) + feats output, merged ----------------
__global__ void k_final(const float* __restrict__ g2, const float* __restrict__ bt2,
                        float* __restrict__ out) {
    extern __shared__ float sg[];            // 125*128 floats (roipool blocks)
    __shared__ float ssc[128], ssh[128];
    __shared__ float tt[32][33];
    int blk = blockIdx.x;
    int tid = threadIdx.x;                   // 512
    if (tid < 128) {
        float m = g_stats[768 + tid] * (1.f / 4096.f);
        float v = g_stats[896 + tid] * (1.f / 4096.f) - m * m;
        float sc = g2[tid] * rsqrtf(v + EPSv);
        ssc[tid] = sc; ssh[tid] = bt2[tid] - m * sc;
    }
    __syncthreads();
    if (blk < BB * RRoi) {
        // ---- roipool: BN3+ReLU applied on the fly while reading h3 ----
        int br = blk;
        int b = br >> 7;
        for (int i = tid; i < 125 * C1v / 4; i += 512)
            ((float4*)sg)[i] = make_float4(0.f, 0.f, 0.f, 0.f);
        __syncthreads();
        const float* H = g_h3 + (size_t)b * NN * C1v;
        const int* lst = g_roilst + (size_t)br * NN;
        int m = g_roicnt[br];
        int ch = tid & 127;
        int slot = tid >> 7;
        float sc = ssc[ch], sh = ssh[ch];
        for (int e = slot; e < m; e += 4) {
            int pk = lst[e];
            int n = pk & 4095;
            int vox = pk >> 12;
            float val = fmaxf(H[(size_t)n * C1v + ch] * sc + sh, 0.f);
            atomicMax((int*)&sg[vox * C1v + ch], __float_as_int(val));
        }
        __syncthreads();
        float4* og = (float4*)(out + FEATS_SZ + (size_t)br * 125 * C1v);
        for (int i = tid; i < 125 * C1v / 4; i += 512) og[i] = ((float4*)sg)[i];
    } else {
        // ---- feats: out[b][c][n] = relu(bn3(h3[b][n][c])), 32x32 tile transpose ----
        int q = blk - BB * RRoi;             // 0..511
        int b = q >> 8;
        int rest = q & 255;
        int n0 = (rest & 63) * 32, o0 = (rest >> 6) * 32;
        int tx = tid & 31, ty = tid >> 5;    // 32 x 16
        #pragma unroll
        for (int r = 0; r < 2; r++) {
            int n_l = ty + r * 16;
            int o = o0 + tx;
            float f = fmaxf(g_h3[(size_t)(b * NN + n0 + n_l) * C1v + o] * ssc[o] + ssh[o], 0.f);
            tt[n_l][tx] = f;
        }
        __syncthreads();
        #pragma unroll
        for (int r = 0; r < 2; r++) {
            int o_l = ty + r * 16;
            out[(size_t)(b * C1v + o0 + o_l) * NN + n0 + tx] = tt[tx][o_l];
        }
    }
}

// ---------------- launch ----------------
extern "C" void kernel_launch(void* const* d_in, const int* in_sizes, int n_in,
                              void* d_out, int out_size) {
    const float* pts    = (const float*)d_in[0];
    const float* feat   = (const float*)d_in[1];
    const float* rois   = (const float*)d_in[2];
    const float* W_mlp  = (const float*)d_in[3];
    const float* g_mlp  = (const float*)d_in[4];
    const float* btm    = (const float*)d_in[5];
    const float* W1     = (const float*)d_in[6];
    const float* b1     = (const float*)d_in[7];
    const float* g1     = (const float*)d_in[8];
    const float* bt1    = (const float*)d_in[9];
    const float* W2     = (const float*)d_in[10];
    const float* b2     = (const float*)d_in[11];
    const float* g2     = (const float*)d_in[12];
    const float* bt2    = (const float*)d_in[13];
    float* out = (float*)d_out;

    cudaFuncSetAttribute(k_final, cudaFuncAttributeMaxDynamicSharedMemorySize,
                         125 * C1v * sizeof(float));

    k_front<<<1507, 256>>>(pts, rois, feat, W_mlp, W1, W2);
    k_gemmG<<<dim3(NN / 64, 256 / 32, BB), 128>>>();
    k_gathermax<<<dim3(NN / PPB, BB), 256>>>(pts);
    k_conv1<<<BB * NN / 16, 256>>>(g_mlp, btm);
    k_gemm1<<<dim3(NN / 64, C1v / 32, BB), 128>>>(b1);
    k_conv2<<<BB * NN / 32, 256>>>(g1, bt1);
    k_gemm2<<<dim3(NN / 64, C1v / 32, BB), 128>>>(b2);
    k_final<<<BB * RRoi + 512, 512, 125 * C1v * sizeof(float)>>>(g2, bt2, out);
}